// round 13
// baseline (speedup 1.0000x reference)
#include <cuda_runtime.h>
#include <cuda_fp16.h>
#include <cstdint>

// Problem constants
#define Sq   1024
#define Dm   1024
#define HDd  64
#define BHh  64
#define NTOK 4096

// ---------------- scratch (device globals; no allocation allowed) ----------
__device__ __half g_h16[17u<<20];   // [0,12M): q,k,v fp16; [12M,17M): Wq,Wk,Wv,Wfq,Wfk fp16
__device__ __half g_QKV[3u<<22];    // Q,K,V head-split fp16 [bh][s][64] (Q pre-scaled)
__device__ __half g_X[2u<<22];      // XQ, XK fp16 [b][s][h*64+d]
__device__ float  g_O[2u<<22];      // OQ, OK fp32

// ---------------- helpers ---------------------------------------------------
__device__ __forceinline__ uint32_t smem_u32(const void* p) {
    return (uint32_t)__cvta_generic_to_shared(p);
}
#define CP16(dst, src) \
    asm volatile("cp.async.cg.shared.global [%0], [%1], 16;\n" :: "r"(dst), "l"(src))
#define CPC() asm volatile("cp.async.commit_group;\n" ::: "memory")
#define CPW(n) asm volatile("cp.async.wait_group %0;\n" :: "n"(n) : "memory")

#define LDSM4(r0,r1,r2,r3,a) \
    asm volatile("ldmatrix.sync.aligned.m8n8.x4.shared.b16 {%0,%1,%2,%3}, [%4];" \
        : "=r"(r0),"=r"(r1),"=r"(r2),"=r"(r3) : "r"(a))
#define LDSM4T(r0,r1,r2,r3,a) \
    asm volatile("ldmatrix.sync.aligned.m8n8.x4.trans.shared.b16 {%0,%1,%2,%3}, [%4];" \
        : "=r"(r0),"=r"(r1),"=r"(r2),"=r"(r3) : "r"(a))

__device__ __forceinline__ void mma16(float c[4],
    uint32_t a0, uint32_t a1, uint32_t a2, uint32_t a3, uint32_t b0, uint32_t b1)
{
    asm volatile(
        "mma.sync.aligned.m16n8k16.row.col.f32.f16.f16.f32 "
        "{%0,%1,%2,%3}, {%4,%5,%6,%7}, {%8,%9}, {%0,%1,%2,%3};\n"
        : "+f"(c[0]), "+f"(c[1]), "+f"(c[2]), "+f"(c[3])
        : "r"(a0), "r"(a1), "r"(a2), "r"(a3), "r"(b0), "r"(b1));
}

// fp16-accumulator HMMA (2x rate class on most SMs)
__device__ __forceinline__ void mma16h(uint32_t c[2],
    uint32_t a0, uint32_t a1, uint32_t a2, uint32_t a3, uint32_t b0, uint32_t b1)
{
    asm volatile(
        "mma.sync.aligned.m16n8k16.row.col.f16.f16.f16.f16 "
        "{%0,%1}, {%2,%3,%4,%5}, {%6,%7}, {%0,%1};\n"
        : "+r"(c[0]), "+r"(c[1])
        : "r"(a0), "r"(a1), "r"(a2), "r"(a3), "r"(b0), "r"(b1));
}

__device__ __forceinline__ uint32_t packh2(float a, float b) {
    __half2 h = __floats2half2_rn(a, b);
    return *(uint32_t*)&h;
}
__device__ __forceinline__ uint32_t exp2h2(uint32_t x) {
    uint32_t r;
    asm("ex2.approx.f16x2 %0, %1;" : "=r"(r) : "r"(x));
    return r;
}
__device__ __forceinline__ float2 h2f2(uint32_t x) {
    return __half22float2(*(__half2*)&x);
}

// ---------------------------------------------------------------------------
// fp32 -> fp16 convert pass. z: 0-2 inputs (4M elems), 3-7 weights (1M elems).
// ---------------------------------------------------------------------------
struct CvtPtrs { const float* p[8]; };
__global__ void __launch_bounds__(256) convert_all(CvtPtrs cp, __half* __restrict__ dst)
{
    int z = blockIdx.y;
    long long n   = (z < 3) ? (1LL << 22) : (1LL << 20);
    long long off = (z < 3) ? ((long long)z << 22)
                            : ((12LL << 20) + ((long long)(z - 3) << 20));
    long long i = ((long long)blockIdx.x * 256 + threadIdx.x) * 8;
    if (i >= n) return;
    const float4* s = (const float4*)(cp.p[z] + i);
    float4 v0 = s[0], v1 = s[1];
    __half2 h0 = __floats2half2_rn(v0.x, v0.y), h1 = __floats2half2_rn(v0.z, v0.w);
    __half2 h2 = __floats2half2_rn(v1.x, v1.y), h3 = __floats2half2_rn(v1.z, v1.w);
    uint4 u;
    u.x = *(uint32_t*)&h0; u.y = *(uint32_t*)&h1;
    u.z = *(uint32_t*)&h2; u.w = *(uint32_t*)&h3;
    *(uint4*)(dst + off + i) = u;
}

// ---------------------------------------------------------------------------
// fp16 NT GEMM (R11 config): C = A.B^T + bias. 128x128 tile, 8 warps (2x4),
// warp 64x32, k-chunk 32, 4 stages, paired iterations (one barrier / 2 chunks).
// Dynamic smem 81920 (2 CTAs/SM).
// MODE 0: fp32 out (output projections); MODE 1: fp16 head-split out (QKV;
//         z==0 (Q) epilogue folds the softmax scale 0.125*log2e).
// ---------------------------------------------------------------------------
template <int MODE>
__global__ void __launch_bounds__(256, 2) tgemm16(
    const __half* __restrict__ A, const __half* __restrict__ B,
    const float* b0p, const float* b1p, const float* b2p,
    void* __restrict__ Cv,
    long long sA, long long sB, long long sC)
{
    constexpr int K = 1024, KITERS = 32;
    extern __shared__ __align__(16) unsigned char smx[];
    const uint32_t base = smem_u32(smx);

    const int z = blockIdx.z;
    A += z * sA;
    B += z * sB;

    const int tid = threadIdx.x, lane = tid & 31, wid = tid >> 5;
    const int bm = blockIdx.y * 128, bn = blockIdx.x * 128;
    const int wm = (wid & 1) * 64, wn = (wid >> 1) * 32;
    const int lg = lane >> 2, lk = lane & 3;

    const int crow = tid >> 2, ccol = tid & 3;
    const __half* Ag0 = A + (long long)(bm + crow) * K + ccol * 8;
    const __half* Ag1 = Ag0 + (long long)64 * K;
    const __half* Bg0 = B + (long long)(bn + crow) * K + ccol * 8;
    const __half* Bg1 = Bg0 + (long long)64 * K;
    const uint32_t dA0 = base + crow * 80 + ccol * 16;
    const uint32_t dA1 = dA0 + 64 * 80;
    const uint32_t dB0 = dA0 + 10240;
    const uint32_t dB1 = dB0 + 64 * 80;

    const uint32_t aoff = base + (uint32_t)(wm + (lane & 15)) * 80 + (lane >> 4) * 16;
    const uint32_t boff = base + 10240 +
        (uint32_t)(wn + (lane & 7) + ((lane & 16) >> 1)) * 80 + ((lane & 8) << 1);

    float acc[4][4][4];
#pragma unroll
    for (int i = 0; i < 4; i++)
#pragma unroll
        for (int j = 0; j < 4; j++)
#pragma unroll
            for (int r = 0; r < 4; r++) acc[i][j][r] = 0.f;

    auto load_chunk = [&](int c) {
        int ko = c << 5;
        uint32_t so = (uint32_t)(c & 3) * 20480u;
        CP16(dA0 + so, Ag0 + ko); CP16(dA1 + so, Ag1 + ko);
        CP16(dB0 + so, Bg0 + ko); CP16(dB1 + so, Bg1 + ko);
    };
    auto compute_chunk = [&](uint32_t sb) {
#pragma unroll
        for (int kx = 0; kx < 2; kx++) {
            uint32_t af[4][4], bf[4][2];
#pragma unroll
            for (int mi = 0; mi < 4; mi++)
                LDSM4(af[mi][0], af[mi][1], af[mi][2], af[mi][3],
                      aoff + sb + mi * 1280 + kx * 32);
#pragma unroll
            for (int pr = 0; pr < 2; pr++) {
                uint32_t r0, r1, r2, r3;
                LDSM4(r0, r1, r2, r3, boff + sb + pr * 1280 + kx * 32);
                bf[pr * 2][0] = r0; bf[pr * 2][1] = r1;
                bf[pr * 2 + 1][0] = r2; bf[pr * 2 + 1][1] = r3;
            }
#pragma unroll
            for (int mi = 0; mi < 4; mi++)
#pragma unroll
                for (int ni = 0; ni < 4; ni++)
                    mma16(acc[mi][ni], af[mi][0], af[mi][1], af[mi][2], af[mi][3],
                          bf[ni][0], bf[ni][1]);
        }
    };

    load_chunk(0); load_chunk(1); CPC();

    for (int it = 0; it < KITERS; it += 2) {
        CPW(0);
        __syncthreads();
        if (it + 2 < KITERS) {
            load_chunk(it + 2);
            load_chunk(it + 3);
            CPC();
        }
        compute_chunk((uint32_t)(it & 3) * 20480u);
        compute_chunk((uint32_t)((it + 1) & 3) * 20480u);
    }

    const float* bias = (z == 0) ? b0p : (z == 1) ? b1p : b2p;
    const float cs = (MODE == 1 && z == 0) ? 0.18033688f : 1.0f;  // 0.125*log2(e)
#pragma unroll
    for (int ni = 0; ni < 4; ni++) {
        int c0 = bn + wn + ni * 8 + lk * 2;
        float bz0 = bias[c0], bz1 = bias[c0 + 1];
#pragma unroll
        for (int mi = 0; mi < 4; mi++) {
            int r0 = bm + wm + mi * 16 + lg;
            float v00 = (acc[mi][ni][0] + bz0) * cs;
            float v01 = (acc[mi][ni][1] + bz1) * cs;
            float v10 = (acc[mi][ni][2] + bz0) * cs;
            float v11 = (acc[mi][ni][3] + bz1) * cs;
            if (MODE == 1) {
                __half* C = (__half*)Cv + z * sC;
                int h = c0 >> 6, d = c0 & 63;
                long long i0 = (((long long)((r0 >> 10) * 16 + h)) << 16) + ((long long)(r0 & 1023) << 6) + d;
                long long i1 = (((long long)(((r0 + 8) >> 10) * 16 + h)) << 16) + ((long long)((r0 + 8) & 1023) << 6) + d;
                *(__half2*)(C + i0) = __floats2half2_rn(v00, v01);
                *(__half2*)(C + i1) = __floats2half2_rn(v10, v11);
            } else {
                float* C = (float*)Cv + z * sC;
                *(float2*)(C + (long long)r0 * 1024 + c0)       = make_float2(v00, v01);
                *(float2*)(C + (long long)(r0 + 8) * 1024 + c0) = make_float2(v10, v11);
            }
        }
    }
}

// ---------------------------------------------------------------------------
// Fused flash-style attention v5: 512 threads, 4 stages, paired iterations.
// S-MMA stays fp32-acc; PV uses fp16-acc HMMA (chained per chunk, flushed to
// fp32 per chunk); z via cvt+FADD on the idle FMA pipe (no ones-MMA).
// Q pre-scaled by 0.125*log2e so exp = ex2 of raw accumulator.
// grid (8 row-tiles, 2 dirs, 64 heads). Smem: A 18432 + 4 x 36864 = 165888.
// ---------------------------------------------------------------------------
__global__ void __launch_bounds__(512, 1) fused_av(
    const __half* __restrict__ Qh, const __half* __restrict__ Kh,
    const __half* __restrict__ Vh, __half* __restrict__ Xout)
{
    extern __shared__ __align__(16) unsigned char smf[];
    const uint32_t base = smem_u32(smf);

    const int qt = blockIdx.x, dir = blockIdx.y, bh = blockIdx.z;
    const __half* Ag = (dir ? Kh : Qh) + ((long long)bh << 16);
    const __half* Bg = (dir ? Qh : Kh) + ((long long)bh << 16);
    const __half* Vg = Vh + ((long long)bh << 16);
    __half* out = Xout + ((long long)dir << 22);

    const int tid = threadIdx.x, lane = tid & 31, wid = tid >> 5;
    const int lg = lane >> 2, lk = lane & 3;
    const int kh = wid & 1, strip = wid >> 1;

    const int ldr = tid >> 2, ldc = tid & 3;
    auto load_tile = [&](uint32_t dst, const __half* src) {
        const __half* s = src + ldr * 64 + ldc * 16;
        uint32_t d = dst + ldr * 144 + ldc * 32;
        CP16(d, s); CP16(d + 16, s + 8);
    };

    const uint32_t smA = base;                 // 18432
    const uint32_t smK0 = base + 18432;        // 4 stages x 36864; V at +18432

    auto load_kv = [&](int c) {
        uint32_t so = (uint32_t)(c & 3) * 36864u;
        load_tile(smK0 + so, Bg + c * 8192);
        load_tile(smK0 + so + 18432, Vg + c * 8192);
    };

    load_tile(smA, Ag + qt * 8192);
    load_kv(0); load_kv(1);
    CPC();

    const uint32_t aoff = smA + (uint32_t)(strip * 16 + (lane & 15)) * 144 + (lane >> 4) * 16;
    const uint32_t blane = (uint32_t)(kh * 64 + (lane & 7) + ((lane & 16) >> 1)) * 144 + ((lane & 8) << 1);
    const uint32_t vlane = (uint32_t)(kh * 64 + (lane & 7) + (lane & 8)) * 144 + (lane >> 4) * 16;

    float oacc[8][4];
#pragma unroll
    for (int i = 0; i < 8; i++)
#pragma unroll
        for (int r = 0; r < 4; r++) oacc[i][r] = 0.f;
    float z0 = 0.f, z1 = 0.f;     // row lg / row lg+8 partial sums (this lane's cols)
    uint32_t qa[4][4];

    auto compute_kv = [&](uint32_t sb) {
        const uint32_t kb = smK0 + sb;
        const uint32_t vb = kb + 18432;
        // S = A.B^T : warp tile 16 x 64, fp32 accumulators (log2-domain logits)
        float sacc[8][4];
#pragma unroll
        for (int i = 0; i < 8; i++)
#pragma unroll
            for (int r = 0; r < 4; r++) sacc[i][r] = 0.f;
#pragma unroll
        for (int g = 0; g < 4; g++) {
#pragma unroll
            for (int ks = 0; ks < 4; ks++) {
                uint32_t r0, r1, r2, r3;
                LDSM4(r0, r1, r2, r3, kb + blane + g * 2304 + ks * 32);
                mma16(sacc[2 * g],     qa[ks][0], qa[ks][1], qa[ks][2], qa[ks][3], r0, r1);
                mma16(sacc[2 * g + 1], qa[ks][0], qa[ks][1], qa[ks][2], qa[ks][3], r2, r3);
            }
        }
        // ex2; z via fp32 FADD; PV via fp16-acc HMMA chained over the chunk
        uint32_t oh[8][2];
#pragma unroll
        for (int i = 0; i < 8; i++) { oh[i][0] = 0u; oh[i][1] = 0u; }
#pragma unroll
        for (int ks2 = 0; ks2 < 4; ks2++) {
            uint32_t pa0 = exp2h2(packh2(sacc[2 * ks2][0],     sacc[2 * ks2][1]));
            uint32_t pa1 = exp2h2(packh2(sacc[2 * ks2][2],     sacc[2 * ks2][3]));
            uint32_t pa2 = exp2h2(packh2(sacc[2 * ks2 + 1][0], sacc[2 * ks2 + 1][1]));
            uint32_t pa3 = exp2h2(packh2(sacc[2 * ks2 + 1][2], sacc[2 * ks2 + 1][3]));
            // z: pa0,pa2 belong to row lg; pa1,pa3 to row lg+8
            float2 f0 = h2f2(pa0), f1 = h2f2(pa1), f2 = h2f2(pa2), f3 = h2f2(pa3);
            z0 += (f0.x + f0.y) + (f2.x + f2.y);
            z1 += (f1.x + f1.y) + (f3.x + f3.y);
#pragma unroll
            for (int dg = 0; dg < 4; dg++) {
                uint32_t v0, v1, v2, v3;
                LDSM4T(v0, v1, v2, v3, vb + vlane + ks2 * 2304 + dg * 32);
                mma16h(oh[2 * dg],     pa0, pa1, pa2, pa3, v0, v1);
                mma16h(oh[2 * dg + 1], pa0, pa1, pa2, pa3, v2, v3);
            }
        }
        // flush fp16 chunk accumulators into fp32
#pragma unroll
        for (int i = 0; i < 8; i++) {
            float2 lo = h2f2(oh[i][0]);   // rows lg
            float2 hi = h2f2(oh[i][1]);   // rows lg+8
            oacc[i][0] += lo.x; oacc[i][1] += lo.y;
            oacc[i][2] += hi.x; oacc[i][3] += hi.y;
        }
    };

    for (int it = 0; it < 8; it += 2) {
        CPW(0);
        __syncthreads();
        if (it == 0) {
#pragma unroll
            for (int ks = 0; ks < 4; ks++)
                LDSM4(qa[ks][0], qa[ks][1], qa[ks][2], qa[ks][3], aoff + ks * 32);
        }
        if (it + 2 < 8) {
            load_kv(it + 2);
            load_kv(it + 3);
            CPC();
        }
        compute_kv((uint32_t)(it & 3) * 36864u);
        compute_kv((uint32_t)((it + 1) & 3) * 36864u);
    }

    // reduce z across the 4 lanes sharing a row (lk dimension)
    z0 += __shfl_xor_sync(0xffffffffu, z0, 1);
    z0 += __shfl_xor_sync(0xffffffffu, z0, 2);
    z1 += __shfl_xor_sync(0xffffffffu, z1, 1);
    z1 += __shfl_xor_sync(0xffffffffu, z1, 2);

    // partner reduction: kh=1 stores partials, kh=0 adds + writes out
    __syncthreads();
    unsigned char* red = smf + strip * 4608 + lane * 16;
    if (kh == 1) {
#pragma unroll
        for (int ni = 0; ni < 8; ni++)
            *(float4*)(red + ni * 512) = *(float4*)oacc[ni];
        *(float2*)(red + 4096) = make_float2(z0, z1);
    }
    __syncthreads();
    if (kh == 0) {
#pragma unroll
        for (int ni = 0; ni < 8; ni++) {
            float4 p = *(const float4*)(red + ni * 512);
            oacc[ni][0] += p.x; oacc[ni][1] += p.y;
            oacc[ni][2] += p.z; oacc[ni][3] += p.w;
        }
        float2 pz = *(const float2*)(red + 4096);
        float iz0 = 1.f / (z0 + pz.x);
        float iz1 = 1.f / (z1 + pz.y);

        const int b_ = bh >> 4, h = bh & 15;
        const int row0 = qt * 128 + strip * 16 + lg;
#pragma unroll
        for (int ni = 0; ni < 8; ni++) {
            int col = h * 64 + ni * 8 + lk * 2;
            *(__half2*)(out + ((long long)(b_ * 1024 + row0)) * 1024 + col) =
                __floats2half2_rn(oacc[ni][0] * iz0, oacc[ni][1] * iz0);
            *(__half2*)(out + ((long long)(b_ * 1024 + row0 + 8)) * 1024 + col) =
                __floats2half2_rn(oacc[ni][2] * iz1, oacc[ni][3] * iz1);
        }
    }
}

// ---------------------------------------------------------------------------
// Merged residual+LayerNorm: grid (4096, 2); y selects (Q-out, K-out) params.
// ---------------------------------------------------------------------------
__global__ void __launch_bounds__(256) add_ln2(
    const float* __restrict__ O, const float* __restrict__ residq,
    const float* __restrict__ residk,
    const float* __restrict__ gq, const float* __restrict__ bq,
    const float* __restrict__ gk, const float* __restrict__ bk,
    float* __restrict__ out)
{
    const int y = blockIdx.y;
    long long row = blockIdx.x;
    const float* proj  = O + ((long long)y << 22) + row * Dm;
    const float* resid = (y ? residk : residq) + row * Dm;
    const float* gamma = y ? gk : gq;
    const float* beta  = y ? bk : bq;
    float* o = out + ((long long)y << 22) + row * Dm;

    int t = threadIdx.x;
    float4 pv = ((const float4*)proj)[t];
    float4 rv = ((const float4*)resid)[t];
    float x0 = pv.x + rv.x, x1 = pv.y + rv.y, x2 = pv.z + rv.z, x3 = pv.w + rv.w;
    float s  = x0 + x1 + x2 + x3;
    float ss = x0*x0 + x1*x1 + x2*x2 + x3*x3;
    __shared__ float shs[8], shss[8];
#pragma unroll
    for (int o2 = 16; o2; o2 >>= 1) {
        s  += __shfl_xor_sync(0xffffffffu, s,  o2);
        ss += __shfl_xor_sync(0xffffffffu, ss, o2);
    }
    if ((t & 31) == 0) { shs[t >> 5] = s; shss[t >> 5] = ss; }
    __syncthreads();
    float S_ = 0.f, SS = 0.f;
#pragma unroll
    for (int i = 0; i < 8; i++) { S_ += shs[i]; SS += shss[i]; }
    float mean = S_ * (1.f / Dm);
    float var  = SS * (1.f / Dm) - mean * mean;
    float k = rsqrtf(var + 1e-5f);
    float4 g  = ((const float4*)gamma)[t];
    float4 be = ((const float4*)beta)[t];
    float4 o4;
    o4.x = (x0 - mean) * k * g.x + be.x;
    o4.y = (x1 - mean) * k * g.y + be.y;
    o4.z = (x2 - mean) * k * g.z + be.z;
    o4.w = (x3 - mean) * k * g.w + be.w;
    ((float4*)o)[t] = o4;
}

// ---------------------------------------------------------------------------
extern "C" void kernel_launch(void* const* d_in, const int* in_sizes, int n_in,
                              void* d_out, int out_size)
{
    const float* query = (const float*)d_in[0];
    const float* key   = (const float*)d_in[1];
    const float* value = (const float*)d_in[2];
    const float* Wq  = (const float*)d_in[3];
    const float* bq  = (const float*)d_in[4];
    const float* Wk  = (const float*)d_in[5];
    const float* bk  = (const float*)d_in[6];
    const float* Wv  = (const float*)d_in[7];
    const float* bv  = (const float*)d_in[8];
    const float* Wfq = (const float*)d_in[9];
    const float* bfq = (const float*)d_in[10];
    const float* Wfk = (const float*)d_in[11];
    const float* bfk = (const float*)d_in[12];
    const float* gq  = (const float*)d_in[13];
    const float* btq = (const float*)d_in[14];
    const float* gk  = (const float*)d_in[15];
    const float* btk = (const float*)d_in[16];

    __half *H16, *QKV, *X;
    float *O;
    cudaGetSymbolAddress((void**)&H16, g_h16);
    cudaGetSymbolAddress((void**)&QKV, g_QKV);
    cudaGetSymbolAddress((void**)&X,   g_X);
    cudaGetSymbolAddress((void**)&O,   g_O);

    float* out = (float*)d_out;

    cudaFuncSetAttribute((const void*)tgemm16<1>,
                         cudaFuncAttributeMaxDynamicSharedMemorySize, 81920);
    cudaFuncSetAttribute((const void*)tgemm16<0>,
                         cudaFuncAttributeMaxDynamicSharedMemorySize, 81920);
    cudaFuncSetAttribute((const void*)fused_av,
                         cudaFuncAttributeMaxDynamicSharedMemorySize, 165888);

    CvtPtrs cp;
    cp.p[0] = query; cp.p[1] = key; cp.p[2] = value;
    cp.p[3] = Wq; cp.p[4] = Wk; cp.p[5] = Wv; cp.p[6] = Wfq; cp.p[7] = Wfk;
    convert_all<<<dim3(2048, 8), 256>>>(cp, H16);

    // QKV projections (z=0..2) -> head-split fp16 (Q pre-scaled by 0.125*log2e)
    tgemm16<1><<<dim3(8, 32, 3), 256, 81920>>>(
        H16, H16 + (12LL << 20), bq, bk, bv, QKV,
        1LL << 22, 1LL << 20, 1LL << 22);

    // Fused attention: both directions; PV on fp16-acc HMMA, z on FMA pipe
    fused_av<<<dim3(8, 2, BHh), 512, 165888>>>(
        QKV, QKV + (1LL << 22), QKV + (2LL << 22), X);

    // Output projections (z=0..1) -> fp32
    tgemm16<0><<<dim3(8, 32, 2), 256, 81920>>>(
        X, H16 + (15LL << 20), bfq, bfk, nullptr, O,
        1LL << 22, 1LL << 20, 1LL << 22);

    // Merged residual + LayerNorm -> both outputs
    add_ln2<<<dim3(NTOK, 2), 256>>>(O, query, key, gq, btq, gk, btk, out);
}

// round 14
// speedup vs baseline: 1.0247x; 1.0247x over previous
#include <cuda_runtime.h>
#include <cuda_fp16.h>
#include <cstdint>

// Problem constants
#define Sq   1024
#define Dm   1024
#define HDd  64
#define BHh  64
#define NTOK 4096

// ---------------- scratch (device globals; no allocation allowed) ----------
__device__ __half g_h16[17u<<20];   // [0,12M): q,k,v fp16; [12M,17M): Wq,Wk,Wv,Wfq,Wfk fp16
__device__ __half g_QKV[3u<<22];    // Q,K,V head-split fp16 [bh][s][64] (Q pre-scaled)
__device__ __half g_X[2u<<22];      // XQ, XK fp16 [b][s][h*64+d]
__device__ __half g_O[2u<<22];      // OQ, OK fp16

// ---------------- helpers ---------------------------------------------------
__device__ __forceinline__ uint32_t smem_u32(const void* p) {
    return (uint32_t)__cvta_generic_to_shared(p);
}
#define CP16(dst, src) \
    asm volatile("cp.async.cg.shared.global [%0], [%1], 16;\n" :: "r"(dst), "l"(src))
#define CPC() asm volatile("cp.async.commit_group;\n" ::: "memory")
#define CPW(n) asm volatile("cp.async.wait_group %0;\n" :: "n"(n) : "memory")

#define LDSM4(r0,r1,r2,r3,a) \
    asm volatile("ldmatrix.sync.aligned.m8n8.x4.shared.b16 {%0,%1,%2,%3}, [%4];" \
        : "=r"(r0),"=r"(r1),"=r"(r2),"=r"(r3) : "r"(a))
#define LDSM4T(r0,r1,r2,r3,a) \
    asm volatile("ldmatrix.sync.aligned.m8n8.x4.trans.shared.b16 {%0,%1,%2,%3}, [%4];" \
        : "=r"(r0),"=r"(r1),"=r"(r2),"=r"(r3) : "r"(a))

__device__ __forceinline__ void mma16(float c[4],
    uint32_t a0, uint32_t a1, uint32_t a2, uint32_t a3, uint32_t b0, uint32_t b1)
{
    asm volatile(
        "mma.sync.aligned.m16n8k16.row.col.f32.f16.f16.f32 "
        "{%0,%1,%2,%3}, {%4,%5,%6,%7}, {%8,%9}, {%0,%1,%2,%3};\n"
        : "+f"(c[0]), "+f"(c[1]), "+f"(c[2]), "+f"(c[3])
        : "r"(a0), "r"(a1), "r"(a2), "r"(a3), "r"(b0), "r"(b1));
}

__device__ __forceinline__ uint32_t packh2(float a, float b) {
    __half2 h = __floats2half2_rn(a, b);
    return *(uint32_t*)&h;
}
__device__ __forceinline__ uint32_t exp2h2(uint32_t x) {
    uint32_t r;
    asm("ex2.approx.f16x2 %0, %1;" : "=r"(r) : "r"(x));
    return r;
}
__device__ __forceinline__ float2 h2f2(uint32_t x) {
    return __half22float2(*(__half2*)&x);
}

// ---------------------------------------------------------------------------
// fp32 -> fp16 convert pass. z: 0-2 inputs (4M elems), 3-7 weights (1M elems).
// ---------------------------------------------------------------------------
struct CvtPtrs { const float* p[8]; };
__global__ void __launch_bounds__(256) convert_all(CvtPtrs cp, __half* __restrict__ dst)
{
    int z = blockIdx.y;
    long long n   = (z < 3) ? (1LL << 22) : (1LL << 20);
    long long off = (z < 3) ? ((long long)z << 22)
                            : ((12LL << 20) + ((long long)(z - 3) << 20));
    long long i = ((long long)blockIdx.x * 256 + threadIdx.x) * 8;
    if (i >= n) return;
    const float4* s = (const float4*)(cp.p[z] + i);
    float4 v0 = s[0], v1 = s[1];
    __half2 h0 = __floats2half2_rn(v0.x, v0.y), h1 = __floats2half2_rn(v0.z, v0.w);
    __half2 h2 = __floats2half2_rn(v1.x, v1.y), h3 = __floats2half2_rn(v1.z, v1.w);
    uint4 u;
    u.x = *(uint32_t*)&h0; u.y = *(uint32_t*)&h1;
    u.z = *(uint32_t*)&h2; u.w = *(uint32_t*)&h3;
    *(uint4*)(dst + off + i) = u;
}

// ---------------------------------------------------------------------------
// fp16 NT GEMM (R11 config): C = A.B^T + bias. 128x128 tile, 8 warps (2x4),
// warp 64x32, k-chunk 32, 4 stages, paired iterations (one barrier / 2 chunks).
// Dynamic smem 81920 (2 CTAs/SM).
// MODE 0: fp16 out flat (output projections);
// MODE 1: fp16 head-split out (QKV; z==0 folds softmax scale 0.125*log2e).
// ---------------------------------------------------------------------------
template <int MODE>
__global__ void __launch_bounds__(256, 2) tgemm16(
    const __half* __restrict__ A, const __half* __restrict__ B,
    const float* b0p, const float* b1p, const float* b2p,
    __half* __restrict__ C,
    long long sA, long long sB, long long sC)
{
    constexpr int K = 1024, KITERS = 32;
    extern __shared__ __align__(16) unsigned char smx[];
    const uint32_t base = smem_u32(smx);

    const int z = blockIdx.z;
    A += z * sA;
    B += z * sB;
    C += z * sC;

    const int tid = threadIdx.x, lane = tid & 31, wid = tid >> 5;
    const int bm = blockIdx.y * 128, bn = blockIdx.x * 128;
    const int wm = (wid & 1) * 64, wn = (wid >> 1) * 32;
    const int lg = lane >> 2, lk = lane & 3;

    const int crow = tid >> 2, ccol = tid & 3;
    const __half* Ag0 = A + (long long)(bm + crow) * K + ccol * 8;
    const __half* Ag1 = Ag0 + (long long)64 * K;
    const __half* Bg0 = B + (long long)(bn + crow) * K + ccol * 8;
    const __half* Bg1 = Bg0 + (long long)64 * K;
    const uint32_t dA0 = base + crow * 80 + ccol * 16;
    const uint32_t dA1 = dA0 + 64 * 80;
    const uint32_t dB0 = dA0 + 10240;
    const uint32_t dB1 = dB0 + 64 * 80;

    const uint32_t aoff = base + (uint32_t)(wm + (lane & 15)) * 80 + (lane >> 4) * 16;
    const uint32_t boff = base + 10240 +
        (uint32_t)(wn + (lane & 7) + ((lane & 16) >> 1)) * 80 + ((lane & 8) << 1);

    float acc[4][4][4];
#pragma unroll
    for (int i = 0; i < 4; i++)
#pragma unroll
        for (int j = 0; j < 4; j++)
#pragma unroll
            for (int r = 0; r < 4; r++) acc[i][j][r] = 0.f;

    auto load_chunk = [&](int c) {
        int ko = c << 5;
        uint32_t so = (uint32_t)(c & 3) * 20480u;
        CP16(dA0 + so, Ag0 + ko); CP16(dA1 + so, Ag1 + ko);
        CP16(dB0 + so, Bg0 + ko); CP16(dB1 + so, Bg1 + ko);
    };
    auto compute_chunk = [&](uint32_t sb) {
#pragma unroll
        for (int kx = 0; kx < 2; kx++) {
            uint32_t af[4][4], bf[4][2];
#pragma unroll
            for (int mi = 0; mi < 4; mi++)
                LDSM4(af[mi][0], af[mi][1], af[mi][2], af[mi][3],
                      aoff + sb + mi * 1280 + kx * 32);
#pragma unroll
            for (int pr = 0; pr < 2; pr++) {
                uint32_t r0, r1, r2, r3;
                LDSM4(r0, r1, r2, r3, boff + sb + pr * 1280 + kx * 32);
                bf[pr * 2][0] = r0; bf[pr * 2][1] = r1;
                bf[pr * 2 + 1][0] = r2; bf[pr * 2 + 1][1] = r3;
            }
#pragma unroll
            for (int mi = 0; mi < 4; mi++)
#pragma unroll
                for (int ni = 0; ni < 4; ni++)
                    mma16(acc[mi][ni], af[mi][0], af[mi][1], af[mi][2], af[mi][3],
                          bf[ni][0], bf[ni][1]);
        }
    };

    load_chunk(0); load_chunk(1); CPC();

    for (int it = 0; it < KITERS; it += 2) {
        CPW(0);
        __syncthreads();
        if (it + 2 < KITERS) {
            load_chunk(it + 2);
            load_chunk(it + 3);
            CPC();
        }
        compute_chunk((uint32_t)(it & 3) * 20480u);
        compute_chunk((uint32_t)((it + 1) & 3) * 20480u);
    }

    const float* bias = (z == 0) ? b0p : (z == 1) ? b1p : b2p;
    const float cs = (MODE == 1 && z == 0) ? 0.18033688f : 1.0f;  // 0.125*log2(e)
#pragma unroll
    for (int ni = 0; ni < 4; ni++) {
        int c0 = bn + wn + ni * 8 + lk * 2;
        float bz0 = bias[c0], bz1 = bias[c0 + 1];
#pragma unroll
        for (int mi = 0; mi < 4; mi++) {
            int r0 = bm + wm + mi * 16 + lg;
            float v00 = (acc[mi][ni][0] + bz0) * cs;
            float v01 = (acc[mi][ni][1] + bz1) * cs;
            float v10 = (acc[mi][ni][2] + bz0) * cs;
            float v11 = (acc[mi][ni][3] + bz1) * cs;
            if (MODE == 1) {
                int h = c0 >> 6, d = c0 & 63;
                long long i0 = (((long long)((r0 >> 10) * 16 + h)) << 16) + ((long long)(r0 & 1023) << 6) + d;
                long long i1 = (((long long)(((r0 + 8) >> 10) * 16 + h)) << 16) + ((long long)((r0 + 8) & 1023) << 6) + d;
                *(__half2*)(C + i0) = __floats2half2_rn(v00, v01);
                *(__half2*)(C + i1) = __floats2half2_rn(v10, v11);
            } else {
                *(__half2*)(C + (long long)r0 * 1024 + c0)       = __floats2half2_rn(v00, v01);
                *(__half2*)(C + (long long)(r0 + 8) * 1024 + c0) = __floats2half2_rn(v10, v11);
            }
        }
    }
}

// ---------------------------------------------------------------------------
// Fused flash-style attention (R11 structure): 512 threads, 4 stages, paired
// iterations. Q pre-scaled by 0.125*log2e (ex2 of raw accumulator).
// ONLY change vs R11: z accumulated on the FMA pipe (cvt+FADD) instead of a
// ones-MMA — removes 2.1 GF from the saturated tensor pipe.
// grid (8 row-tiles, 2 dirs, 64 heads). Smem: A 18432 + 4 x 36864 = 165888.
// ---------------------------------------------------------------------------
__global__ void __launch_bounds__(512, 1) fused_av(
    const __half* __restrict__ Qh, const __half* __restrict__ Kh,
    const __half* __restrict__ Vh, __half* __restrict__ Xout)
{
    extern __shared__ __align__(16) unsigned char smf[];
    const uint32_t base = smem_u32(smf);

    const int qt = blockIdx.x, dir = blockIdx.y, bh = blockIdx.z;
    const __half* Ag = (dir ? Kh : Qh) + ((long long)bh << 16);
    const __half* Bg = (dir ? Qh : Kh) + ((long long)bh << 16);
    const __half* Vg = Vh + ((long long)bh << 16);
    __half* out = Xout + ((long long)dir << 22);

    const int tid = threadIdx.x, lane = tid & 31, wid = tid >> 5;
    const int lg = lane >> 2, lk = lane & 3;
    const int kh = wid & 1, strip = wid >> 1;

    const int ldr = tid >> 2, ldc = tid & 3;
    auto load_tile = [&](uint32_t dst, const __half* src) {
        const __half* s = src + ldr * 64 + ldc * 16;
        uint32_t d = dst + ldr * 144 + ldc * 32;
        CP16(d, s); CP16(d + 16, s + 8);
    };

    const uint32_t smA = base;                 // 18432
    const uint32_t smK0 = base + 18432;        // 4 stages x 36864; V at +18432

    auto load_kv = [&](int c) {
        uint32_t so = (uint32_t)(c & 3) * 36864u;
        load_tile(smK0 + so, Bg + c * 8192);
        load_tile(smK0 + so + 18432, Vg + c * 8192);
    };

    load_tile(smA, Ag + qt * 8192);
    load_kv(0); load_kv(1);
    CPC();

    const uint32_t aoff = smA + (uint32_t)(strip * 16 + (lane & 15)) * 144 + (lane >> 4) * 16;
    const uint32_t blane = (uint32_t)(kh * 64 + (lane & 7) + ((lane & 16) >> 1)) * 144 + ((lane & 8) << 1);
    const uint32_t vlane = (uint32_t)(kh * 64 + (lane & 7) + (lane & 8)) * 144 + (lane >> 4) * 16;

    float oacc[8][4];
#pragma unroll
    for (int i = 0; i < 8; i++)
#pragma unroll
        for (int r = 0; r < 4; r++) oacc[i][r] = 0.f;
    float z0 = 0.f, z1 = 0.f;     // rows lg / lg+8, this lane's columns
    uint32_t qa[4][4];

    auto compute_kv = [&](uint32_t sb) {
        const uint32_t kb = smK0 + sb;
        const uint32_t vb = kb + 18432;
        float sacc[8][4];
#pragma unroll
        for (int i = 0; i < 8; i++)
#pragma unroll
            for (int r = 0; r < 4; r++) sacc[i][r] = 0.f;
#pragma unroll
        for (int g = 0; g < 4; g++) {
#pragma unroll
            for (int ks = 0; ks < 4; ks++) {
                uint32_t r0, r1, r2, r3;
                LDSM4(r0, r1, r2, r3, kb + blane + g * 2304 + ks * 32);
                mma16(sacc[2 * g],     qa[ks][0], qa[ks][1], qa[ks][2], qa[ks][3], r0, r1);
                mma16(sacc[2 * g + 1], qa[ks][0], qa[ks][1], qa[ks][2], qa[ks][3], r2, r3);
            }
        }
#pragma unroll
        for (int ks2 = 0; ks2 < 4; ks2++) {
            uint32_t pa0 = exp2h2(packh2(sacc[2 * ks2][0],     sacc[2 * ks2][1]));
            uint32_t pa1 = exp2h2(packh2(sacc[2 * ks2][2],     sacc[2 * ks2][3]));
            uint32_t pa2 = exp2h2(packh2(sacc[2 * ks2 + 1][0], sacc[2 * ks2 + 1][1]));
            uint32_t pa3 = exp2h2(packh2(sacc[2 * ks2 + 1][2], sacc[2 * ks2 + 1][3]));
            // z on FMA pipe: pa0,pa2 are row lg; pa1,pa3 are row lg+8
            float2 f0 = h2f2(pa0), f1 = h2f2(pa1), f2 = h2f2(pa2), f3 = h2f2(pa3);
            z0 += (f0.x + f0.y) + (f2.x + f2.y);
            z1 += (f1.x + f1.y) + (f3.x + f3.y);
#pragma unroll
            for (int dg = 0; dg < 4; dg++) {
                uint32_t v0, v1, v2, v3;
                LDSM4T(v0, v1, v2, v3, vb + vlane + ks2 * 2304 + dg * 32);
                mma16(oacc[2 * dg],     pa0, pa1, pa2, pa3, v0, v1);
                mma16(oacc[2 * dg + 1], pa0, pa1, pa2, pa3, v2, v3);
            }
        }
    };

    for (int it = 0; it < 8; it += 2) {
        CPW(0);
        __syncthreads();
        if (it == 0) {
#pragma unroll
            for (int ks = 0; ks < 4; ks++)
                LDSM4(qa[ks][0], qa[ks][1], qa[ks][2], qa[ks][3], aoff + ks * 32);
        }
        if (it + 2 < 8) {
            load_kv(it + 2);
            load_kv(it + 3);
            CPC();
        }
        compute_kv((uint32_t)(it & 3) * 36864u);
        compute_kv((uint32_t)((it + 1) & 3) * 36864u);
    }

    // reduce z across the 4 lanes sharing a row
    z0 += __shfl_xor_sync(0xffffffffu, z0, 1);
    z0 += __shfl_xor_sync(0xffffffffu, z0, 2);
    z1 += __shfl_xor_sync(0xffffffffu, z1, 1);
    z1 += __shfl_xor_sync(0xffffffffu, z1, 2);

    // partner reduction: kh=1 stores partials, kh=0 adds + writes out
    __syncthreads();
    unsigned char* red = smf + strip * 4608 + lane * 16;
    if (kh == 1) {
#pragma unroll
        for (int ni = 0; ni < 8; ni++)
            *(float4*)(red + ni * 512) = *(float4*)oacc[ni];
        *(float2*)(red + 4096) = make_float2(z0, z1);
    }
    __syncthreads();
    if (kh == 0) {
#pragma unroll
        for (int ni = 0; ni < 8; ni++) {
            float4 p = *(const float4*)(red + ni * 512);
            oacc[ni][0] += p.x; oacc[ni][1] += p.y;
            oacc[ni][2] += p.z; oacc[ni][3] += p.w;
        }
        float2 pz = *(const float2*)(red + 4096);
        float iz0 = 1.f / (z0 + pz.x);
        float iz1 = 1.f / (z1 + pz.y);

        const int b_ = bh >> 4, h = bh & 15;
        const int row0 = qt * 128 + strip * 16 + lg;
#pragma unroll
        for (int ni = 0; ni < 8; ni++) {
            int col = h * 64 + ni * 8 + lk * 2;
            *(__half2*)(out + ((long long)(b_ * 1024 + row0)) * 1024 + col) =
                __floats2half2_rn(oacc[ni][0] * iz0, oacc[ni][1] * iz0);
            *(__half2*)(out + ((long long)(b_ * 1024 + row0 + 8)) * 1024 + col) =
                __floats2half2_rn(oacc[ni][2] * iz1, oacc[ni][3] * iz1);
        }
    }
}

// ---------------------------------------------------------------------------
// Merged residual+LayerNorm (proj now fp16): grid (4096, 2).
// ---------------------------------------------------------------------------
__global__ void __launch_bounds__(256) add_ln2(
    const __half* __restrict__ O, const float* __restrict__ residq,
    const float* __restrict__ residk,
    const float* __restrict__ gq, const float* __restrict__ bq,
    const float* __restrict__ gk, const float* __restrict__ bk,
    float* __restrict__ out)
{
    const int y = blockIdx.y;
    long long row = blockIdx.x;
    const __half* proj = O + ((long long)y << 22) + row * Dm;
    const float* resid = (y ? residk : residq) + row * Dm;
    const float* gamma = y ? gk : gq;
    const float* beta  = y ? bk : bq;
    float* o = out + ((long long)y << 22) + row * Dm;

    int t = threadIdx.x;
    uint2 pu = ((const uint2*)proj)[t];            // 4 halves
    float2 p01 = h2f2(pu.x), p23 = h2f2(pu.y);
    float4 rv = ((const float4*)resid)[t];
    float x0 = p01.x + rv.x, x1 = p01.y + rv.y, x2 = p23.x + rv.z, x3 = p23.y + rv.w;
    float s  = x0 + x1 + x2 + x3;
    float ss = x0*x0 + x1*x1 + x2*x2 + x3*x3;
    __shared__ float shs[8], shss[8];
#pragma unroll
    for (int o2 = 16; o2; o2 >>= 1) {
        s  += __shfl_xor_sync(0xffffffffu, s,  o2);
        ss += __shfl_xor_sync(0xffffffffu, ss, o2);
    }
    if ((t & 31) == 0) { shs[t >> 5] = s; shss[t >> 5] = ss; }
    __syncthreads();
    float S_ = 0.f, SS = 0.f;
#pragma unroll
    for (int i = 0; i < 8; i++) { S_ += shs[i]; SS += shss[i]; }
    float mean = S_ * (1.f / Dm);
    float var  = SS * (1.f / Dm) - mean * mean;
    float k = rsqrtf(var + 1e-5f);
    float4 g  = ((const float4*)gamma)[t];
    float4 be = ((const float4*)beta)[t];
    float4 o4;
    o4.x = (x0 - mean) * k * g.x + be.x;
    o4.y = (x1 - mean) * k * g.y + be.y;
    o4.z = (x2 - mean) * k * g.z + be.z;
    o4.w = (x3 - mean) * k * g.w + be.w;
    ((float4*)o)[t] = o4;
}

// ---------------------------------------------------------------------------
extern "C" void kernel_launch(void* const* d_in, const int* in_sizes, int n_in,
                              void* d_out, int out_size)
{
    const float* query = (const float*)d_in[0];
    const float* key   = (const float*)d_in[1];
    const float* value = (const float*)d_in[2];
    const float* Wq  = (const float*)d_in[3];
    const float* bq  = (const float*)d_in[4];
    const float* Wk  = (const float*)d_in[5];
    const float* bk  = (const float*)d_in[6];
    const float* Wv  = (const float*)d_in[7];
    const float* bv  = (const float*)d_in[8];
    const float* Wfq = (const float*)d_in[9];
    const float* bfq = (const float*)d_in[10];
    const float* Wfk = (const float*)d_in[11];
    const float* bfk = (const float*)d_in[12];
    const float* gq  = (const float*)d_in[13];
    const float* btq = (const float*)d_in[14];
    const float* gk  = (const float*)d_in[15];
    const float* btk = (const float*)d_in[16];

    __half *H16, *QKV, *X, *O;
    cudaGetSymbolAddress((void**)&H16, g_h16);
    cudaGetSymbolAddress((void**)&QKV, g_QKV);
    cudaGetSymbolAddress((void**)&X,   g_X);
    cudaGetSymbolAddress((void**)&O,   g_O);

    float* out = (float*)d_out;

    cudaFuncSetAttribute((const void*)tgemm16<1>,
                         cudaFuncAttributeMaxDynamicSharedMemorySize, 81920);
    cudaFuncSetAttribute((const void*)tgemm16<0>,
                         cudaFuncAttributeMaxDynamicSharedMemorySize, 81920);
    cudaFuncSetAttribute((const void*)fused_av,
                         cudaFuncAttributeMaxDynamicSharedMemorySize, 165888);

    CvtPtrs cp;
    cp.p[0] = query; cp.p[1] = key; cp.p[2] = value;
    cp.p[3] = Wq; cp.p[4] = Wk; cp.p[5] = Wv; cp.p[6] = Wfq; cp.p[7] = Wfk;
    convert_all<<<dim3(2048, 8), 256>>>(cp, H16);

    // QKV projections (z=0..2) -> head-split fp16 (Q pre-scaled by 0.125*log2e)
    tgemm16<1><<<dim3(8, 32, 3), 256, 81920>>>(
        H16, H16 + (12LL << 20), bq, bk, bv, QKV,
        1LL << 22, 1LL << 20, 1LL << 22);

    // Fused attention: both directions; z on FMA pipe
    fused_av<<<dim3(8, 2, BHh), 512, 165888>>>(
        QKV, QKV + (1LL << 22), QKV + (2LL << 22), X);

    // Output projections (z=0..1) -> fp16
    tgemm16<0><<<dim3(8, 32, 2), 256, 81920>>>(
        X, H16 + (15LL << 20), bfq, bfk, nullptr, O,
        1LL << 22, 1LL << 20, 1LL << 22);

    // Merged residual + LayerNorm -> both outputs
    add_ln2<<<dim3(NTOK, 2), 256>>>(O, query, key, gq, btq, gk, btk, out);
}

// round 15
// speedup vs baseline: 1.0309x; 1.0061x over previous
#include <cuda_runtime.h>
#include <cuda_fp16.h>
#include <cstdint>

// Problem constants
#define Sq   1024
#define Dm   1024
#define HDd  64
#define BHh  64
#define NTOK 4096

// ---------------- scratch (device globals; no allocation allowed) ----------
__device__ __half g_h16[17u<<20];   // [0,12M): q,k,v fp16; [12M,17M): Wq,Wk,Wv,Wfq,Wfk fp16
__device__ __half g_QKV[3u<<22];    // Q,K,V head-split fp16 [bh][s][64] (Q pre-scaled)
__device__ __half g_X[2u<<22];      // XQ, XK fp16 [b][s][h*64+d]
__device__ __half g_O[2u<<22];      // OQ, OK fp16

// ---------------- helpers ---------------------------------------------------
__device__ __forceinline__ uint32_t smem_u32(const void* p) {
    return (uint32_t)__cvta_generic_to_shared(p);
}
#define CP16(dst, src) \
    asm volatile("cp.async.cg.shared.global [%0], [%1], 16;\n" :: "r"(dst), "l"(src))
#define CPC() asm volatile("cp.async.commit_group;\n" ::: "memory")
#define CPW(n) asm volatile("cp.async.wait_group %0;\n" :: "n"(n) : "memory")

#define LDSM4(r0,r1,r2,r3,a) \
    asm volatile("ldmatrix.sync.aligned.m8n8.x4.shared.b16 {%0,%1,%2,%3}, [%4];" \
        : "=r"(r0),"=r"(r1),"=r"(r2),"=r"(r3) : "r"(a))
#define LDSM4T(r0,r1,r2,r3,a) \
    asm volatile("ldmatrix.sync.aligned.m8n8.x4.trans.shared.b16 {%0,%1,%2,%3}, [%4];" \
        : "=r"(r0),"=r"(r1),"=r"(r2),"=r"(r3) : "r"(a))

__device__ __forceinline__ void mma16(float c[4],
    uint32_t a0, uint32_t a1, uint32_t a2, uint32_t a3, uint32_t b0, uint32_t b1)
{
    asm volatile(
        "mma.sync.aligned.m16n8k16.row.col.f32.f16.f16.f32 "
        "{%0,%1,%2,%3}, {%4,%5,%6,%7}, {%8,%9}, {%0,%1,%2,%3};\n"
        : "+f"(c[0]), "+f"(c[1]), "+f"(c[2]), "+f"(c[3])
        : "r"(a0), "r"(a1), "r"(a2), "r"(a3), "r"(b0), "r"(b1));
}

__device__ __forceinline__ uint32_t packh2(float a, float b) {
    __half2 h = __floats2half2_rn(a, b);
    return *(uint32_t*)&h;
}
__device__ __forceinline__ uint32_t exp2h2(uint32_t x) {
    uint32_t r;
    asm("ex2.approx.f16x2 %0, %1;" : "=r"(r) : "r"(x));
    return r;
}
__device__ __forceinline__ float2 h2f2(uint32_t x) {
    return __half22float2(*(__half2*)&x);
}

// ---------------------------------------------------------------------------
// fp32 -> fp16 convert pass. z: 0-2 inputs (4M elems), 3-7 weights (1M elems).
// ---------------------------------------------------------------------------
struct CvtPtrs { const float* p[8]; };
__global__ void __launch_bounds__(256) convert_all(CvtPtrs cp, __half* __restrict__ dst)
{
    int z = blockIdx.y;
    long long n   = (z < 3) ? (1LL << 22) : (1LL << 20);
    long long off = (z < 3) ? ((long long)z << 22)
                            : ((12LL << 20) + ((long long)(z - 3) << 20));
    long long i = ((long long)blockIdx.x * 256 + threadIdx.x) * 8;
    if (i >= n) return;
    const float4* s = (const float4*)(cp.p[z] + i);
    float4 v0 = s[0], v1 = s[1];
    __half2 h0 = __floats2half2_rn(v0.x, v0.y), h1 = __floats2half2_rn(v0.z, v0.w);
    __half2 h2 = __floats2half2_rn(v1.x, v1.y), h3 = __floats2half2_rn(v1.z, v1.w);
    uint4 u;
    u.x = *(uint32_t*)&h0; u.y = *(uint32_t*)&h1;
    u.z = *(uint32_t*)&h2; u.w = *(uint32_t*)&h3;
    *(uint4*)(dst + off + i) = u;
}

// ---------------------------------------------------------------------------
// fp16 NT GEMM (R11 config): C = A.B^T + bias. 128x128 tile, 8 warps (2x4),
// warp 64x32, k-chunk 32, 4 stages, paired iterations (one barrier / 2 chunks).
// Dynamic smem 81920 (2 CTAs/SM).
// MODE 0: fp16 out flat (output projections);
// MODE 1: fp16 head-split out (QKV; z==0 folds softmax scale 0.125*log2e).
// ---------------------------------------------------------------------------
template <int MODE>
__global__ void __launch_bounds__(256, 2) tgemm16(
    const __half* __restrict__ A, const __half* __restrict__ B,
    const float* b0p, const float* b1p, const float* b2p,
    __half* __restrict__ C,
    long long sA, long long sB, long long sC)
{
    constexpr int K = 1024, KITERS = 32;
    extern __shared__ __align__(16) unsigned char smx[];
    const uint32_t base = smem_u32(smx);

    const int z = blockIdx.z;
    A += z * sA;
    B += z * sB;
    C += z * sC;

    const int tid = threadIdx.x, lane = tid & 31, wid = tid >> 5;
    const int bm = blockIdx.y * 128, bn = blockIdx.x * 128;
    const int wm = (wid & 1) * 64, wn = (wid >> 1) * 32;
    const int lg = lane >> 2, lk = lane & 3;

    const int crow = tid >> 2, ccol = tid & 3;
    const __half* Ag0 = A + (long long)(bm + crow) * K + ccol * 8;
    const __half* Ag1 = Ag0 + (long long)64 * K;
    const __half* Bg0 = B + (long long)(bn + crow) * K + ccol * 8;
    const __half* Bg1 = Bg0 + (long long)64 * K;
    const uint32_t dA0 = base + crow * 80 + ccol * 16;
    const uint32_t dA1 = dA0 + 64 * 80;
    const uint32_t dB0 = dA0 + 10240;
    const uint32_t dB1 = dB0 + 64 * 80;

    const uint32_t aoff = base + (uint32_t)(wm + (lane & 15)) * 80 + (lane >> 4) * 16;
    const uint32_t boff = base + 10240 +
        (uint32_t)(wn + (lane & 7) + ((lane & 16) >> 1)) * 80 + ((lane & 8) << 1);

    float acc[4][4][4];
#pragma unroll
    for (int i = 0; i < 4; i++)
#pragma unroll
        for (int j = 0; j < 4; j++)
#pragma unroll
            for (int r = 0; r < 4; r++) acc[i][j][r] = 0.f;

    auto load_chunk = [&](int c) {
        int ko = c << 5;
        uint32_t so = (uint32_t)(c & 3) * 20480u;
        CP16(dA0 + so, Ag0 + ko); CP16(dA1 + so, Ag1 + ko);
        CP16(dB0 + so, Bg0 + ko); CP16(dB1 + so, Bg1 + ko);
    };
    auto compute_chunk = [&](uint32_t sb) {
#pragma unroll
        for (int kx = 0; kx < 2; kx++) {
            uint32_t af[4][4], bf[4][2];
#pragma unroll
            for (int mi = 0; mi < 4; mi++)
                LDSM4(af[mi][0], af[mi][1], af[mi][2], af[mi][3],
                      aoff + sb + mi * 1280 + kx * 32);
#pragma unroll
            for (int pr = 0; pr < 2; pr++) {
                uint32_t r0, r1, r2, r3;
                LDSM4(r0, r1, r2, r3, boff + sb + pr * 1280 + kx * 32);
                bf[pr * 2][0] = r0; bf[pr * 2][1] = r1;
                bf[pr * 2 + 1][0] = r2; bf[pr * 2 + 1][1] = r3;
            }
#pragma unroll
            for (int mi = 0; mi < 4; mi++)
#pragma unroll
                for (int ni = 0; ni < 4; ni++)
                    mma16(acc[mi][ni], af[mi][0], af[mi][1], af[mi][2], af[mi][3],
                          bf[ni][0], bf[ni][1]);
        }
    };

    load_chunk(0); load_chunk(1); CPC();

    for (int it = 0; it < KITERS; it += 2) {
        CPW(0);
        __syncthreads();
        if (it + 2 < KITERS) {
            load_chunk(it + 2);
            load_chunk(it + 3);
            CPC();
        }
        compute_chunk((uint32_t)(it & 3) * 20480u);
        compute_chunk((uint32_t)((it + 1) & 3) * 20480u);
    }

    const float* bias = (z == 0) ? b0p : (z == 1) ? b1p : b2p;
    const float cs = (MODE == 1 && z == 0) ? 0.18033688f : 1.0f;  // 0.125*log2(e)
#pragma unroll
    for (int ni = 0; ni < 4; ni++) {
        int c0 = bn + wn + ni * 8 + lk * 2;
        float bz0 = bias[c0], bz1 = bias[c0 + 1];
#pragma unroll
        for (int mi = 0; mi < 4; mi++) {
            int r0 = bm + wm + mi * 16 + lg;
            float v00 = (acc[mi][ni][0] + bz0) * cs;
            float v01 = (acc[mi][ni][1] + bz1) * cs;
            float v10 = (acc[mi][ni][2] + bz0) * cs;
            float v11 = (acc[mi][ni][3] + bz1) * cs;
            if (MODE == 1) {
                int h = c0 >> 6, d = c0 & 63;
                long long i0 = (((long long)((r0 >> 10) * 16 + h)) << 16) + ((long long)(r0 & 1023) << 6) + d;
                long long i1 = (((long long)(((r0 + 8) >> 10) * 16 + h)) << 16) + ((long long)((r0 + 8) & 1023) << 6) + d;
                *(__half2*)(C + i0) = __floats2half2_rn(v00, v01);
                *(__half2*)(C + i1) = __floats2half2_rn(v10, v11);
            } else {
                *(__half2*)(C + (long long)r0 * 1024 + c0)       = __floats2half2_rn(v00, v01);
                *(__half2*)(C + (long long)(r0 + 8) * 1024 + c0) = __floats2half2_rn(v10, v11);
            }
        }
    }
}

// ---------------------------------------------------------------------------
// Fused flash-style attention — exact R11 version (fastest measured):
// 512 threads, 4 stages, paired iterations, Q pre-scaled by 0.125*log2e
// (ex2 of raw accumulator), z via ones-MMA (tensor-slack, beats FMA-z).
// grid (8 row-tiles, 2 dirs, 64 heads). Smem: A 18432 + 4 x 36864 = 165888.
// ---------------------------------------------------------------------------
__global__ void __launch_bounds__(512, 1) fused_av(
    const __half* __restrict__ Qh, const __half* __restrict__ Kh,
    const __half* __restrict__ Vh, __half* __restrict__ Xout)
{
    extern __shared__ __align__(16) unsigned char smf[];
    const uint32_t base = smem_u32(smf);
    constexpr uint32_t ONES = 0x3C003C00u;      // half2(1,1)

    const int qt = blockIdx.x, dir = blockIdx.y, bh = blockIdx.z;
    const __half* Ag = (dir ? Kh : Qh) + ((long long)bh << 16);
    const __half* Bg = (dir ? Qh : Kh) + ((long long)bh << 16);
    const __half* Vg = Vh + ((long long)bh << 16);
    __half* out = Xout + ((long long)dir << 22);

    const int tid = threadIdx.x, lane = tid & 31, wid = tid >> 5;
    const int lg = lane >> 2, lk = lane & 3;
    const int kh = wid & 1, strip = wid >> 1;

    const int ldr = tid >> 2, ldc = tid & 3;
    auto load_tile = [&](uint32_t dst, const __half* src) {
        const __half* s = src + ldr * 64 + ldc * 16;
        uint32_t d = dst + ldr * 144 + ldc * 32;
        CP16(d, s); CP16(d + 16, s + 8);
    };

    const uint32_t smA = base;                 // 18432
    const uint32_t smK0 = base + 18432;        // 4 stages x 36864; V at +18432

    auto load_kv = [&](int c) {
        uint32_t so = (uint32_t)(c & 3) * 36864u;
        load_tile(smK0 + so, Bg + c * 8192);
        load_tile(smK0 + so + 18432, Vg + c * 8192);
    };

    load_tile(smA, Ag + qt * 8192);
    load_kv(0); load_kv(1);
    CPC();

    const uint32_t aoff = smA + (uint32_t)(strip * 16 + (lane & 15)) * 144 + (lane >> 4) * 16;
    const uint32_t blane = (uint32_t)(kh * 64 + (lane & 7) + ((lane & 16) >> 1)) * 144 + ((lane & 8) << 1);
    const uint32_t vlane = (uint32_t)(kh * 64 + (lane & 7) + (lane & 8)) * 144 + (lane >> 4) * 16;

    float oacc[8][4];
#pragma unroll
    for (int i = 0; i < 8; i++)
#pragma unroll
        for (int r = 0; r < 4; r++) oacc[i][r] = 0.f;
    float zacc[4] = {0.f, 0.f, 0.f, 0.f};
    uint32_t qa[4][4];

    auto compute_kv = [&](uint32_t sb) {
        const uint32_t kb = smK0 + sb;
        const uint32_t vb = kb + 18432;
        float sacc[8][4];
#pragma unroll
        for (int i = 0; i < 8; i++)
#pragma unroll
            for (int r = 0; r < 4; r++) sacc[i][r] = 0.f;
#pragma unroll
        for (int g = 0; g < 4; g++) {
#pragma unroll
            for (int ks = 0; ks < 4; ks++) {
                uint32_t r0, r1, r2, r3;
                LDSM4(r0, r1, r2, r3, kb + blane + g * 2304 + ks * 32);
                mma16(sacc[2 * g],     qa[ks][0], qa[ks][1], qa[ks][2], qa[ks][3], r0, r1);
                mma16(sacc[2 * g + 1], qa[ks][0], qa[ks][1], qa[ks][2], qa[ks][3], r2, r3);
            }
        }
#pragma unroll
        for (int ks2 = 0; ks2 < 4; ks2++) {
            uint32_t pa0 = exp2h2(packh2(sacc[2 * ks2][0],     sacc[2 * ks2][1]));
            uint32_t pa1 = exp2h2(packh2(sacc[2 * ks2][2],     sacc[2 * ks2][3]));
            uint32_t pa2 = exp2h2(packh2(sacc[2 * ks2 + 1][0], sacc[2 * ks2 + 1][1]));
            uint32_t pa3 = exp2h2(packh2(sacc[2 * ks2 + 1][2], sacc[2 * ks2 + 1][3]));
            mma16(zacc, pa0, pa1, pa2, pa3, ONES, ONES);
#pragma unroll
            for (int dg = 0; dg < 4; dg++) {
                uint32_t v0, v1, v2, v3;
                LDSM4T(v0, v1, v2, v3, vb + vlane + ks2 * 2304 + dg * 32);
                mma16(oacc[2 * dg],     pa0, pa1, pa2, pa3, v0, v1);
                mma16(oacc[2 * dg + 1], pa0, pa1, pa2, pa3, v2, v3);
            }
        }
    };

    for (int it = 0; it < 8; it += 2) {
        CPW(0);
        __syncthreads();
        if (it == 0) {
#pragma unroll
            for (int ks = 0; ks < 4; ks++)
                LDSM4(qa[ks][0], qa[ks][1], qa[ks][2], qa[ks][3], aoff + ks * 32);
        }
        if (it + 2 < 8) {
            load_kv(it + 2);
            load_kv(it + 3);
            CPC();
        }
        compute_kv((uint32_t)(it & 3) * 36864u);
        compute_kv((uint32_t)((it + 1) & 3) * 36864u);
    }

    __syncthreads();
    unsigned char* red = smf + strip * 4608 + lane * 16;
    if (kh == 1) {
#pragma unroll
        for (int ni = 0; ni < 8; ni++)
            *(float4*)(red + ni * 512) = *(float4*)oacc[ni];
        *(float4*)(red + 4096) = *(float4*)zacc;
    }
    __syncthreads();
    if (kh == 0) {
#pragma unroll
        for (int ni = 0; ni < 8; ni++) {
            float4 p = *(const float4*)(red + ni * 512);
            oacc[ni][0] += p.x; oacc[ni][1] += p.y;
            oacc[ni][2] += p.z; oacc[ni][3] += p.w;
        }
        float4 pz = *(const float4*)(red + 4096);
        float iz0 = 1.f / (zacc[0] + pz.x);
        float iz1 = 1.f / (zacc[2] + pz.z);

        const int b_ = bh >> 4, h = bh & 15;
        const int row0 = qt * 128 + strip * 16 + lg;
#pragma unroll
        for (int ni = 0; ni < 8; ni++) {
            int col = h * 64 + ni * 8 + lk * 2;
            *(__half2*)(out + ((long long)(b_ * 1024 + row0)) * 1024 + col) =
                __floats2half2_rn(oacc[ni][0] * iz0, oacc[ni][1] * iz0);
            *(__half2*)(out + ((long long)(b_ * 1024 + row0 + 8)) * 1024 + col) =
                __floats2half2_rn(oacc[ni][2] * iz1, oacc[ni][3] * iz1);
        }
    }
}

// ---------------------------------------------------------------------------
// Merged residual+LayerNorm (proj fp16): grid (4096, 2).
// ---------------------------------------------------------------------------
__global__ void __launch_bounds__(256) add_ln2(
    const __half* __restrict__ O, const float* __restrict__ residq,
    const float* __restrict__ residk,
    const float* __restrict__ gq, const float* __restrict__ bq,
    const float* __restrict__ gk, const float* __restrict__ bk,
    float* __restrict__ out)
{
    const int y = blockIdx.y;
    long long row = blockIdx.x;
    const __half* proj = O + ((long long)y << 22) + row * Dm;
    const float* resid = (y ? residk : residq) + row * Dm;
    const float* gamma = y ? gk : gq;
    const float* beta  = y ? bk : bq;
    float* o = out + ((long long)y << 22) + row * Dm;

    int t = threadIdx.x;
    uint2 pu = ((const uint2*)proj)[t];
    float2 p01 = h2f2(pu.x), p23 = h2f2(pu.y);
    float4 rv = ((const float4*)resid)[t];
    float x0 = p01.x + rv.x, x1 = p01.y + rv.y, x2 = p23.x + rv.z, x3 = p23.y + rv.w;
    float s  = x0 + x1 + x2 + x3;
    float ss = x0*x0 + x1*x1 + x2*x2 + x3*x3;
    __shared__ float shs[8], shss[8];
#pragma unroll
    for (int o2 = 16; o2; o2 >>= 1) {
        s  += __shfl_xor_sync(0xffffffffu, s,  o2);
        ss += __shfl_xor_sync(0xffffffffu, ss, o2);
    }
    if ((t & 31) == 0) { shs[t >> 5] = s; shss[t >> 5] = ss; }
    __syncthreads();
    float S_ = 0.f, SS = 0.f;
#pragma unroll
    for (int i = 0; i < 8; i++) { S_ += shs[i]; SS += shss[i]; }
    float mean = S_ * (1.f / Dm);
    float var  = SS * (1.f / Dm) - mean * mean;
    float k = rsqrtf(var + 1e-5f);
    float4 g  = ((const float4*)gamma)[t];
    float4 be = ((const float4*)beta)[t];
    float4 o4;
    o4.x = (x0 - mean) * k * g.x + be.x;
    o4.y = (x1 - mean) * k * g.y + be.y;
    o4.z = (x2 - mean) * k * g.z + be.z;
    o4.w = (x3 - mean) * k * g.w + be.w;
    ((float4*)o)[t] = o4;
}

// ---------------------------------------------------------------------------
extern "C" void kernel_launch(void* const* d_in, const int* in_sizes, int n_in,
                              void* d_out, int out_size)
{
    const float* query = (const float*)d_in[0];
    const float* key   = (const float*)d_in[1];
    const float* value = (const float*)d_in[2];
    const float* Wq  = (const float*)d_in[3];
    const float* bq  = (const float*)d_in[4];
    const float* Wk  = (const float*)d_in[5];
    const float* bk  = (const float*)d_in[6];
    const float* Wv  = (const float*)d_in[7];
    const float* bv  = (const float*)d_in[8];
    const float* Wfq = (const float*)d_in[9];
    const float* bfq = (const float*)d_in[10];
    const float* Wfk = (const float*)d_in[11];
    const float* bfk = (const float*)d_in[12];
    const float* gq  = (const float*)d_in[13];
    const float* btq = (const float*)d_in[14];
    const float* gk  = (const float*)d_in[15];
    const float* btk = (const float*)d_in[16];

    __half *H16, *QKV, *X, *O;
    cudaGetSymbolAddress((void**)&H16, g_h16);
    cudaGetSymbolAddress((void**)&QKV, g_QKV);
    cudaGetSymbolAddress((void**)&X,   g_X);
    cudaGetSymbolAddress((void**)&O,   g_O);

    float* out = (float*)d_out;

    cudaFuncSetAttribute((const void*)tgemm16<1>,
                         cudaFuncAttributeMaxDynamicSharedMemorySize, 81920);
    cudaFuncSetAttribute((const void*)tgemm16<0>,
                         cudaFuncAttributeMaxDynamicSharedMemorySize, 81920);
    cudaFuncSetAttribute((const void*)fused_av,
                         cudaFuncAttributeMaxDynamicSharedMemorySize, 165888);

    CvtPtrs cp;
    cp.p[0] = query; cp.p[1] = key; cp.p[2] = value;
    cp.p[3] = Wq; cp.p[4] = Wk; cp.p[5] = Wv; cp.p[6] = Wfq; cp.p[7] = Wfk;
    convert_all<<<dim3(2048, 8), 256>>>(cp, H16);

    // QKV projections (z=0..2) -> head-split fp16 (Q pre-scaled by 0.125*log2e)
    tgemm16<1><<<dim3(8, 32, 3), 256, 81920>>>(
        H16, H16 + (12LL << 20), bq, bk, bv, QKV,
        1LL << 22, 1LL << 20, 1LL << 22);

    // Fused attention: both directions (R11 config, ones-MMA z)
    fused_av<<<dim3(8, 2, BHh), 512, 165888>>>(
        QKV, QKV + (1LL << 22), QKV + (2LL << 22), X);

    // Output projections (z=0..1) -> fp16
    tgemm16<0><<<dim3(8, 32, 2), 256, 81920>>>(
        X, H16 + (15LL << 20), bfq, bfk, nullptr, O,
        1LL << 22, 1LL << 20, 1LL << 22);

    // Merged residual + LayerNorm -> both outputs
    add_ln2<<<dim3(NTOK, 2), 256>>>(O, query, key, gq, btq, gk, btk, out);
}

// round 16
// speedup vs baseline: 1.0784x; 1.0460x over previous
#include <cuda_runtime.h>
#include <cuda_fp16.h>
#include <cstdint>

// Problem constants
#define Sq   1024
#define Dm   1024
#define HDd  64
#define BHh  64
#define NTOK 4096

// ---------------- scratch (device globals; no allocation allowed) ----------
__device__ __half g_h16[17u<<20];   // [0,12M): q,k,v fp16; [12M,17M): Wq,Wk,Wv,Wfq,Wfk fp16
__device__ __half g_QKV[3u<<22];    // Q,K,V head-split fp16 [bh][s][64] (Q pre-scaled)
__device__ __half g_X[2u<<22];      // XQ, XK fp16 [b][s][h*64+d]
__device__ __half g_O[2u<<22];      // OQ, OK fp16

// ---------------- helpers ---------------------------------------------------
__device__ __forceinline__ uint32_t smem_u32(const void* p) {
    return (uint32_t)__cvta_generic_to_shared(p);
}
#define CP16(dst, src) \
    asm volatile("cp.async.cg.shared.global [%0], [%1], 16;\n" :: "r"(dst), "l"(src))
#define CPC() asm volatile("cp.async.commit_group;\n" ::: "memory")
#define CPW(n) asm volatile("cp.async.wait_group %0;\n" :: "n"(n) : "memory")

#define LDSM4(r0,r1,r2,r3,a) \
    asm volatile("ldmatrix.sync.aligned.m8n8.x4.shared.b16 {%0,%1,%2,%3}, [%4];" \
        : "=r"(r0),"=r"(r1),"=r"(r2),"=r"(r3) : "r"(a))
#define LDSM4T(r0,r1,r2,r3,a) \
    asm volatile("ldmatrix.sync.aligned.m8n8.x4.trans.shared.b16 {%0,%1,%2,%3}, [%4];" \
        : "=r"(r0),"=r"(r1),"=r"(r2),"=r"(r3) : "r"(a))

__device__ __forceinline__ void mma16(float c[4],
    uint32_t a0, uint32_t a1, uint32_t a2, uint32_t a3, uint32_t b0, uint32_t b1)
{
    asm volatile(
        "mma.sync.aligned.m16n8k16.row.col.f32.f16.f16.f32 "
        "{%0,%1,%2,%3}, {%4,%5,%6,%7}, {%8,%9}, {%0,%1,%2,%3};\n"
        : "+f"(c[0]), "+f"(c[1]), "+f"(c[2]), "+f"(c[3])
        : "r"(a0), "r"(a1), "r"(a2), "r"(a3), "r"(b0), "r"(b1));
}

__device__ __forceinline__ uint32_t packh2(float a, float b) {
    __half2 h = __floats2half2_rn(a, b);
    return *(uint32_t*)&h;
}
__device__ __forceinline__ uint32_t exp2h2(uint32_t x) {
    uint32_t r;
    asm("ex2.approx.f16x2 %0, %1;" : "=r"(r) : "r"(x));
    return r;
}
__device__ __forceinline__ float2 h2f2(uint32_t x) {
    return __half22float2(*(__half2*)&x);
}
__device__ __forceinline__ __half2 u2h2(uint32_t x) { return *(__half2*)&x; }

// ---------------------------------------------------------------------------
// fp32 -> fp16 converts, exact-sized: inputs (4M elems x3), weights (1M x5).
// ---------------------------------------------------------------------------
struct CvtPtrs { const float* p[8]; };
__global__ void __launch_bounds__(256) convert_in(CvtPtrs cp, __half* __restrict__ dst)
{
    int z = blockIdx.y;
    long long i = ((long long)blockIdx.x * 256 + threadIdx.x) * 8;
    const float4* s = (const float4*)(cp.p[z] + i);
    float4 v0 = s[0], v1 = s[1];
    uint4 u;
    u.x = packh2(v0.x, v0.y); u.y = packh2(v0.z, v0.w);
    u.z = packh2(v1.x, v1.y); u.w = packh2(v1.z, v1.w);
    *(uint4*)(dst + ((long long)z << 22) + i) = u;
}
__global__ void __launch_bounds__(256) convert_w(CvtPtrs cp, __half* __restrict__ dst)
{
    int z = blockIdx.y;
    long long i = ((long long)blockIdx.x * 256 + threadIdx.x) * 8;
    const float4* s = (const float4*)(cp.p[3 + z] + i);
    float4 v0 = s[0], v1 = s[1];
    uint4 u;
    u.x = packh2(v0.x, v0.y); u.y = packh2(v0.z, v0.w);
    u.z = packh2(v1.x, v1.y); u.w = packh2(v1.z, v1.w);
    *(uint4*)(dst + (12LL << 20) + ((long long)z << 20) + i) = u;
}

// ---------------------------------------------------------------------------
// fp16 NT GEMM (R11 config): C = A.B^T + bias. 128x128 tile, 8 warps (2x4),
// warp 64x32, k-chunk 32, 4 stages, paired iterations (one barrier / 2 chunks).
// Dynamic smem 81920 (2 CTAs/SM).
// MODE 0: fp16 out flat (output projections);
// MODE 1: fp16 head-split out (QKV; z==0 folds softmax scale 0.125*log2e).
// ---------------------------------------------------------------------------
template <int MODE>
__global__ void __launch_bounds__(256, 2) tgemm16(
    const __half* __restrict__ A, const __half* __restrict__ B,
    const float* b0p, const float* b1p, const float* b2p,
    __half* __restrict__ C,
    long long sA, long long sB, long long sC)
{
    constexpr int K = 1024, KITERS = 32;
    extern __shared__ __align__(16) unsigned char smx[];
    const uint32_t base = smem_u32(smx);

    const int z = blockIdx.z;
    A += z * sA;
    B += z * sB;
    C += z * sC;

    const int tid = threadIdx.x, lane = tid & 31, wid = tid >> 5;
    const int bm = blockIdx.y * 128, bn = blockIdx.x * 128;
    const int wm = (wid & 1) * 64, wn = (wid >> 1) * 32;
    const int lg = lane >> 2, lk = lane & 3;

    const int crow = tid >> 2, ccol = tid & 3;
    const __half* Ag0 = A + (long long)(bm + crow) * K + ccol * 8;
    const __half* Ag1 = Ag0 + (long long)64 * K;
    const __half* Bg0 = B + (long long)(bn + crow) * K + ccol * 8;
    const __half* Bg1 = Bg0 + (long long)64 * K;
    const uint32_t dA0 = base + crow * 80 + ccol * 16;
    const uint32_t dA1 = dA0 + 64 * 80;
    const uint32_t dB0 = dA0 + 10240;
    const uint32_t dB1 = dB0 + 64 * 80;

    const uint32_t aoff = base + (uint32_t)(wm + (lane & 15)) * 80 + (lane >> 4) * 16;
    const uint32_t boff = base + 10240 +
        (uint32_t)(wn + (lane & 7) + ((lane & 16) >> 1)) * 80 + ((lane & 8) << 1);

    float acc[4][4][4];
#pragma unroll
    for (int i = 0; i < 4; i++)
#pragma unroll
        for (int j = 0; j < 4; j++)
#pragma unroll
            for (int r = 0; r < 4; r++) acc[i][j][r] = 0.f;

    auto load_chunk = [&](int c) {
        int ko = c << 5;
        uint32_t so = (uint32_t)(c & 3) * 20480u;
        CP16(dA0 + so, Ag0 + ko); CP16(dA1 + so, Ag1 + ko);
        CP16(dB0 + so, Bg0 + ko); CP16(dB1 + so, Bg1 + ko);
    };
    auto compute_chunk = [&](uint32_t sb) {
#pragma unroll
        for (int kx = 0; kx < 2; kx++) {
            uint32_t af[4][4], bf[4][2];
#pragma unroll
            for (int mi = 0; mi < 4; mi++)
                LDSM4(af[mi][0], af[mi][1], af[mi][2], af[mi][3],
                      aoff + sb + mi * 1280 + kx * 32);
#pragma unroll
            for (int pr = 0; pr < 2; pr++) {
                uint32_t r0, r1, r2, r3;
                LDSM4(r0, r1, r2, r3, boff + sb + pr * 1280 + kx * 32);
                bf[pr * 2][0] = r0; bf[pr * 2][1] = r1;
                bf[pr * 2 + 1][0] = r2; bf[pr * 2 + 1][1] = r3;
            }
#pragma unroll
            for (int mi = 0; mi < 4; mi++)
#pragma unroll
                for (int ni = 0; ni < 4; ni++)
                    mma16(acc[mi][ni], af[mi][0], af[mi][1], af[mi][2], af[mi][3],
                          bf[ni][0], bf[ni][1]);
        }
    };

    load_chunk(0); load_chunk(1); CPC();

    for (int it = 0; it < KITERS; it += 2) {
        CPW(0);
        __syncthreads();
        if (it + 2 < KITERS) {
            load_chunk(it + 2);
            load_chunk(it + 3);
            CPC();
        }
        compute_chunk((uint32_t)(it & 3) * 20480u);
        compute_chunk((uint32_t)((it + 1) & 3) * 20480u);
    }

    const float* bias = (z == 0) ? b0p : (z == 1) ? b1p : b2p;
    const float cs = (MODE == 1 && z == 0) ? 0.18033688f : 1.0f;  // 0.125*log2(e)
#pragma unroll
    for (int ni = 0; ni < 4; ni++) {
        int c0 = bn + wn + ni * 8 + lk * 2;
        float bz0 = bias[c0], bz1 = bias[c0 + 1];
#pragma unroll
        for (int mi = 0; mi < 4; mi++) {
            int r0 = bm + wm + mi * 16 + lg;
            float v00 = (acc[mi][ni][0] + bz0) * cs;
            float v01 = (acc[mi][ni][1] + bz1) * cs;
            float v10 = (acc[mi][ni][2] + bz0) * cs;
            float v11 = (acc[mi][ni][3] + bz1) * cs;
            if (MODE == 1) {
                int h = c0 >> 6, d = c0 & 63;
                long long i0 = (((long long)((r0 >> 10) * 16 + h)) << 16) + ((long long)(r0 & 1023) << 6) + d;
                long long i1 = (((long long)(((r0 + 8) >> 10) * 16 + h)) << 16) + ((long long)((r0 + 8) & 1023) << 6) + d;
                *(__half2*)(C + i0) = __floats2half2_rn(v00, v01);
                *(__half2*)(C + i1) = __floats2half2_rn(v10, v11);
            } else {
                *(__half2*)(C + (long long)r0 * 1024 + c0)       = __floats2half2_rn(v00, v01);
                *(__half2*)(C + (long long)(r0 + 8) * 1024 + c0) = __floats2half2_rn(v10, v11);
            }
        }
    }
}

// ---------------------------------------------------------------------------
// Fused flash-style attention v6: R11 structure (512 thr, 4 stages, paired
// iterations, Q pre-scaled so exp = ex2 of raw acc), with the z ones-MMA
// replaced by HADD2 accumulation on the half-ALU pipe (no conversions,
// independent of the PV chain) — removes 2.1 GF from the saturated tensor pipe.
// grid (8 row-tiles, 2 dirs, 64 heads). Smem: A 18432 + 4 x 36864 = 165888.
// ---------------------------------------------------------------------------
__global__ void __launch_bounds__(512, 1) fused_av(
    const __half* __restrict__ Qh, const __half* __restrict__ Kh,
    const __half* __restrict__ Vh, __half* __restrict__ Xout)
{
    extern __shared__ __align__(16) unsigned char smf[];
    const uint32_t base = smem_u32(smf);

    const int qt = blockIdx.x, dir = blockIdx.y, bh = blockIdx.z;
    const __half* Ag = (dir ? Kh : Qh) + ((long long)bh << 16);
    const __half* Bg = (dir ? Qh : Kh) + ((long long)bh << 16);
    const __half* Vg = Vh + ((long long)bh << 16);
    __half* out = Xout + ((long long)dir << 22);

    const int tid = threadIdx.x, lane = tid & 31, wid = tid >> 5;
    const int lg = lane >> 2, lk = lane & 3;
    const int kh = wid & 1, strip = wid >> 1;

    const int ldr = tid >> 2, ldc = tid & 3;
    auto load_tile = [&](uint32_t dst, const __half* src) {
        const __half* s = src + ldr * 64 + ldc * 16;
        uint32_t d = dst + ldr * 144 + ldc * 32;
        CP16(d, s); CP16(d + 16, s + 8);
    };

    const uint32_t smA = base;                 // 18432
    const uint32_t smK0 = base + 18432;        // 4 stages x 36864; V at +18432

    auto load_kv = [&](int c) {
        uint32_t so = (uint32_t)(c & 3) * 36864u;
        load_tile(smK0 + so, Bg + c * 8192);
        load_tile(smK0 + so + 18432, Vg + c * 8192);
    };

    load_tile(smA, Ag + qt * 8192);
    load_kv(0); load_kv(1);
    CPC();

    const uint32_t aoff = smA + (uint32_t)(strip * 16 + (lane & 15)) * 144 + (lane >> 4) * 16;
    const uint32_t blane = (uint32_t)(kh * 64 + (lane & 7) + ((lane & 16) >> 1)) * 144 + ((lane & 8) << 1);
    const uint32_t vlane = (uint32_t)(kh * 64 + (lane & 7) + (lane & 8)) * 144 + (lane >> 4) * 16;

    float oacc[8][4];
#pragma unroll
    for (int i = 0; i < 8; i++)
#pragma unroll
        for (int r = 0; r < 4; r++) oacc[i][r] = 0.f;
    __half2 zh0 = __float2half2_rn(0.f);   // row lg partial sums
    __half2 zh1 = __float2half2_rn(0.f);   // row lg+8 partial sums
    uint32_t qa[4][4];

    auto compute_kv = [&](uint32_t sb) {
        const uint32_t kb = smK0 + sb;
        const uint32_t vb = kb + 18432;
        float sacc[8][4];
#pragma unroll
        for (int i = 0; i < 8; i++)
#pragma unroll
            for (int r = 0; r < 4; r++) sacc[i][r] = 0.f;
#pragma unroll
        for (int g = 0; g < 4; g++) {
#pragma unroll
            for (int ks = 0; ks < 4; ks++) {
                uint32_t r0, r1, r2, r3;
                LDSM4(r0, r1, r2, r3, kb + blane + g * 2304 + ks * 32);
                mma16(sacc[2 * g],     qa[ks][0], qa[ks][1], qa[ks][2], qa[ks][3], r0, r1);
                mma16(sacc[2 * g + 1], qa[ks][0], qa[ks][1], qa[ks][2], qa[ks][3], r2, r3);
            }
        }
#pragma unroll
        for (int ks2 = 0; ks2 < 4; ks2++) {
            uint32_t pa0 = exp2h2(packh2(sacc[2 * ks2][0],     sacc[2 * ks2][1]));
            uint32_t pa1 = exp2h2(packh2(sacc[2 * ks2][2],     sacc[2 * ks2][3]));
            uint32_t pa2 = exp2h2(packh2(sacc[2 * ks2 + 1][0], sacc[2 * ks2 + 1][1]));
            uint32_t pa3 = exp2h2(packh2(sacc[2 * ks2 + 1][2], sacc[2 * ks2 + 1][3]));
            // z on half-ALU pipe: pa0,pa2 = row lg; pa1,pa3 = row lg+8
            zh0 = __hadd2(zh0, __hadd2(u2h2(pa0), u2h2(pa2)));
            zh1 = __hadd2(zh1, __hadd2(u2h2(pa1), u2h2(pa3)));
#pragma unroll
            for (int dg = 0; dg < 4; dg++) {
                uint32_t v0, v1, v2, v3;
                LDSM4T(v0, v1, v2, v3, vb + vlane + ks2 * 2304 + dg * 32);
                mma16(oacc[2 * dg],     pa0, pa1, pa2, pa3, v0, v1);
                mma16(oacc[2 * dg + 1], pa0, pa1, pa2, pa3, v2, v3);
            }
        }
    };

    for (int it = 0; it < 8; it += 2) {
        CPW(0);
        __syncthreads();
        if (it == 0) {
#pragma unroll
            for (int ks = 0; ks < 4; ks++)
                LDSM4(qa[ks][0], qa[ks][1], qa[ks][2], qa[ks][3], aoff + ks * 32);
        }
        if (it + 2 < 8) {
            load_kv(it + 2);
            load_kv(it + 3);
            CPC();
        }
        compute_kv((uint32_t)(it & 3) * 36864u);
        compute_kv((uint32_t)((it + 1) & 3) * 36864u);
    }

    // finalize z: half2 -> float, reduce across the 4 lk lanes of each row
    float2 zf0 = __half22float2(zh0), zf1 = __half22float2(zh1);
    float z0 = zf0.x + zf0.y;
    float z1 = zf1.x + zf1.y;
    z0 += __shfl_xor_sync(0xffffffffu, z0, 1);
    z0 += __shfl_xor_sync(0xffffffffu, z0, 2);
    z1 += __shfl_xor_sync(0xffffffffu, z1, 1);
    z1 += __shfl_xor_sync(0xffffffffu, z1, 2);

    // partner reduction: kh=1 stores partials, kh=0 adds + writes out
    __syncthreads();
    unsigned char* red = smf + strip * 4608 + lane * 16;
    if (kh == 1) {
#pragma unroll
        for (int ni = 0; ni < 8; ni++)
            *(float4*)(red + ni * 512) = *(float4*)oacc[ni];
        *(float2*)(red + 4096) = make_float2(z0, z1);
    }
    __syncthreads();
    if (kh == 0) {
#pragma unroll
        for (int ni = 0; ni < 8; ni++) {
            float4 p = *(const float4*)(red + ni * 512);
            oacc[ni][0] += p.x; oacc[ni][1] += p.y;
            oacc[ni][2] += p.z; oacc[ni][3] += p.w;
        }
        float2 pz = *(const float2*)(red + 4096);
        float iz0 = 1.f / (z0 + pz.x);
        float iz1 = 1.f / (z1 + pz.y);

        const int b_ = bh >> 4, h = bh & 15;
        const int row0 = qt * 128 + strip * 16 + lg;
#pragma unroll
        for (int ni = 0; ni < 8; ni++) {
            int col = h * 64 + ni * 8 + lk * 2;
            *(__half2*)(out + ((long long)(b_ * 1024 + row0)) * 1024 + col) =
                __floats2half2_rn(oacc[ni][0] * iz0, oacc[ni][1] * iz0);
            *(__half2*)(out + ((long long)(b_ * 1024 + row0 + 8)) * 1024 + col) =
                __floats2half2_rn(oacc[ni][2] * iz1, oacc[ni][3] * iz1);
        }
    }
}

// ---------------------------------------------------------------------------
// Merged residual+LayerNorm (proj fp16): grid (4096, 2).
// ---------------------------------------------------------------------------
__global__ void __launch_bounds__(256) add_ln2(
    const __half* __restrict__ O, const float* __restrict__ residq,
    const float* __restrict__ residk,
    const float* __restrict__ gq, const float* __restrict__ bq,
    const float* __restrict__ gk, const float* __restrict__ bk,
    float* __restrict__ out)
{
    const int y = blockIdx.y;
    long long row = blockIdx.x;
    const __half* proj = O + ((long long)y << 22) + row * Dm;
    const float* resid = (y ? residk : residq) + row * Dm;
    const float* gamma = y ? gk : gq;
    const float* beta  = y ? bk : bq;
    float* o = out + ((long long)y << 22) + row * Dm;

    int t = threadIdx.x;
    uint2 pu = ((const uint2*)proj)[t];
    float2 p01 = h2f2(pu.x), p23 = h2f2(pu.y);
    float4 rv = ((const float4*)resid)[t];
    float x0 = p01.x + rv.x, x1 = p01.y + rv.y, x2 = p23.x + rv.z, x3 = p23.y + rv.w;
    float s  = x0 + x1 + x2 + x3;
    float ss = x0*x0 + x1*x1 + x2*x2 + x3*x3;
    __shared__ float shs[8], shss[8];
#pragma unroll
    for (int o2 = 16; o2; o2 >>= 1) {
        s  += __shfl_xor_sync(0xffffffffu, s,  o2);
        ss += __shfl_xor_sync(0xffffffffu, ss, o2);
    }
    if ((t & 31) == 0) { shs[t >> 5] = s; shss[t >> 5] = ss; }
    __syncthreads();
    float S_ = 0.f, SS = 0.f;
#pragma unroll
    for (int i = 0; i < 8; i++) { S_ += shs[i]; SS += shss[i]; }
    float mean = S_ * (1.f / Dm);
    float var  = SS * (1.f / Dm) - mean * mean;
    float k = rsqrtf(var + 1e-5f);
    float4 g  = ((const float4*)gamma)[t];
    float4 be = ((const float4*)beta)[t];
    float4 o4;
    o4.x = (x0 - mean) * k * g.x + be.x;
    o4.y = (x1 - mean) * k * g.y + be.y;
    o4.z = (x2 - mean) * k * g.z + be.z;
    o4.w = (x3 - mean) * k * g.w + be.w;
    ((float4*)o)[t] = o4;
}

// ---------------------------------------------------------------------------
extern "C" void kernel_launch(void* const* d_in, const int* in_sizes, int n_in,
                              void* d_out, int out_size)
{
    const float* query = (const float*)d_in[0];
    const float* key   = (const float*)d_in[1];
    const float* value = (const float*)d_in[2];
    const float* Wq  = (const float*)d_in[3];
    const float* bq  = (const float*)d_in[4];
    const float* Wk  = (const float*)d_in[5];
    const float* bk  = (const float*)d_in[6];
    const float* Wv  = (const float*)d_in[7];
    const float* bv  = (const float*)d_in[8];
    const float* Wfq = (const float*)d_in[9];
    const float* bfq = (const float*)d_in[10];
    const float* Wfk = (const float*)d_in[11];
    const float* bfk = (const float*)d_in[12];
    const float* gq  = (const float*)d_in[13];
    const float* btq = (const float*)d_in[14];
    const float* gk  = (const float*)d_in[15];
    const float* btk = (const float*)d_in[16];

    __half *H16, *QKV, *X, *O;
    cudaGetSymbolAddress((void**)&H16, g_h16);
    cudaGetSymbolAddress((void**)&QKV, g_QKV);
    cudaGetSymbolAddress((void**)&X,   g_X);
    cudaGetSymbolAddress((void**)&O,   g_O);

    float* out = (float*)d_out;

    cudaFuncSetAttribute((const void*)tgemm16<1>,
                         cudaFuncAttributeMaxDynamicSharedMemorySize, 81920);
    cudaFuncSetAttribute((const void*)tgemm16<0>,
                         cudaFuncAttributeMaxDynamicSharedMemorySize, 81920);
    cudaFuncSetAttribute((const void*)fused_av,
                         cudaFuncAttributeMaxDynamicSharedMemorySize, 165888);

    CvtPtrs cp;
    cp.p[0] = query; cp.p[1] = key; cp.p[2] = value;
    cp.p[3] = Wq; cp.p[4] = Wk; cp.p[5] = Wv; cp.p[6] = Wfq; cp.p[7] = Wfk;
    convert_in<<<dim3(2048, 3), 256>>>(cp, H16);
    convert_w <<<dim3(512, 5), 256>>>(cp, H16);

    // QKV projections (z=0..2) -> head-split fp16 (Q pre-scaled by 0.125*log2e)
    tgemm16<1><<<dim3(8, 32, 3), 256, 81920>>>(
        H16, H16 + (12LL << 20), bq, bk, bv, QKV,
        1LL << 22, 1LL << 20, 1LL << 22);

    // Fused attention: both directions; z on half-ALU pipe (no ones-MMA)
    fused_av<<<dim3(8, 2, BHh), 512, 165888>>>(
        QKV, QKV + (1LL << 22), QKV + (2LL << 22), X);

    // Output projections (z=0..1) -> fp16
    tgemm16<0><<<dim3(8, 32, 2), 256, 81920>>>(
        X, H16 + (15LL << 20), bfq, bfk, nullptr, O,
        1LL << 22, 1LL << 20, 1LL << 22);

    // Merged residual + LayerNorm -> both outputs
    add_ln2<<<dim3(NTOK, 2), 256>>>(O, query, key, gq, btq, gk, btk, out);
}